// round 15
// baseline (speedup 1.0000x reference)
#include <cuda_runtime.h>
#include <math.h>
#include <stdint.h>

constexpr float LRF = 0.001f;

// All feature maps stored 36x36 with logical origin (2,2).
// Borders are NEVER written by any kernel -> they remain the zero value that
// __device__ globals get at module load, on every graph replay.
constexpr int NY36 = 4 * 128 * 36 * 36;
constexpr int NRP  = 4 * 64 * 36 * 36;
constexpr int NDOTCTA = 256;

__device__ __align__(16) float g_x36[NRP];
__device__ __align__(16) float g_y0[NY36];
__device__ __align__(16) float g_r0[NRP];
__device__ __align__(16) float g_m1[NRP];
__device__ __align__(16) float g_T[64 * 25 * 64];     // [(a*25+tap)*64 + b]
__device__ __align__(16) float g_WffP[64 * 9 * 128];  // [(ic*9+tap)*128 + oc]
__device__ __align__(16) float g_WfbP1[128 * 9 * 64]; // [(ic*9+tap)*64  + oc]
__device__ __align__(16) float g_WfbP2[64 * 9 * 128]; // [(ic*9+tap)*128 + og], flipped
__device__ double g_part[NDOTCTA * 3];
__device__ float g_w[2];
__device__ unsigned g_ctr;   // ticket counter; reset to 0 by last CTA each run

// ---------------- cp.async helpers ----------------
__device__ __forceinline__ void cpa16(uint32_t d, const void* s) {
    asm volatile("cp.async.cg.shared.global [%0], [%1], 16;" :: "r"(d), "l"(s));
}
__device__ __forceinline__ void cpcommit() { asm volatile("cp.async.commit_group;"); }
__device__ __forceinline__ void cpwait1()  { asm volatile("cp.async.wait_group 1;"); }
__device__ __forceinline__ void cpwait0()  { asm volatile("cp.async.wait_group 0;"); }

// ---------------------------------------------------------------------------
// setup: blocks 0..63  -> tgram (Gram 5x5 kernel of A A^T);
//        blocks 64..127 -> x36 interior fill + weight re-layout (no zeroing)
// ---------------------------------------------------------------------------
__global__ __launch_bounds__(256)
void setup_kernel(const float* __restrict__ x, const float* __restrict__ Wff,
                  const float* __restrict__ Wfb)
{
    __shared__ float red[64 * 25];
    if (blockIdx.x < 64) {
        const int b    = blockIdx.x;
        const int a    = threadIdx.x & 63;
        const int part = threadIdx.x >> 6;

        float acc[25];
        #pragma unroll
        for (int t = 0; t < 25; t++) acc[t] = 0.f;

        for (int o = part * 32; o < part * 32 + 32; o++) {
            float wbv[9], wav[9];
            #pragma unroll
            for (int i = 0; i < 9; i++) {
                wbv[i] = __ldg(Wfb + (o * 64 + b) * 9 + i);
                wav[i] = __ldg(Wfb + (o * 64 + a) * 9 + i);
            }
            #pragma unroll
            for (int du = -2; du <= 2; du++)
                #pragma unroll
                for (int dv = -2; dv <= 2; dv++) {
                    float s = 0.f;
                    #pragma unroll
                    for (int u = 0; u < 3; u++) {
                        if (u - du < 0 || u - du > 2) continue;
                        #pragma unroll
                        for (int v = 0; v < 3; v++) {
                            if (v - dv < 0 || v - dv > 2) continue;
                            s += wbv[u * 3 + v] * wav[(u - du) * 3 + (v - dv)];
                        }
                    }
                    acc[(du + 2) * 5 + (dv + 2)] += s;
                }
        }
        if (part == 3) {
            #pragma unroll
            for (int t = 0; t < 25; t++) red[a * 25 + t] = acc[t];
        }
        __syncthreads();
        if (part == 2) {
            #pragma unroll
            for (int t = 0; t < 25; t++) red[a * 25 + t] += acc[t];
        }
        __syncthreads();
        if (part == 1) {
            #pragma unroll
            for (int t = 0; t < 25; t++) red[a * 25 + t] += acc[t];
        }
        __syncthreads();
        if (part == 0) {
            #pragma unroll
            for (int t = 0; t < 25; t++)
                g_T[((size_t)a * 25 + t) * 64 + b] = acc[t] + red[a * 25 + t];
        }
    } else {
        const int i = (blockIdx.x - 64) * 256 + threadIdx.x;
        const int stride = 64 * 256;
        // x36 interior fill (borders stay zero from static init)
        for (int j = i; j < 4 * 64 * 1024; j += stride) {
            int nc = j >> 10;
            int rc = j & 1023;
            int r = rc >> 5, c = rc & 31;
            g_x36[((size_t)nc * 36 + r + 2) * 36 + c + 2] = __ldg(x + j);
        }
        for (int j = i; j < 73728; j += stride) {
            int oc  = j % 128;
            int tap = (j / 128) % 9;
            int ic  = j / 1152;
            g_WffP[j]  = __ldg(Wff + (oc * 64 + ic) * 9 + tap);
            g_WfbP2[j] = __ldg(Wfb + (oc * 64 + ic) * 9 + (8 - tap));
        }
        for (int j = i; j < 73728; j += stride) {
            int oc  = j % 64;
            int tap = (j / 64) % 9;
            int ic  = j / 576;
            g_WfbP1[j] = __ldg(Wfb + (ic * 64 + oc) * 9 + tap);
        }
    }
}

// ---------------------------------------------------------------------------
// cp.async double-buffered 3x3 conv.  Block 128 = col(32) x ocg(4),
// OCB = OCTOT/4 oc per thread.  CTA output: 4 rows x OCTOT oc.
// Grid (OC/OCTOT, 4, 8)  -- always >= 256 CTAs.
// EPI 1: relu -> padded out.
// EPI 2: x - acc -> padded out.
// EPI 3: FUSED combine: stages BOTH in (r0) and in2 (m1) per chunk and forms
//        s = w0*r0 + w1*m1 in smem; epilogue y0 + acc + 1x1(x,wb) -> raw out.
// ---------------------------------------------------------------------------
template<int IC, int OC, int EPI, int CH, int OCTOT>
__global__ __launch_bounds__(128)
void conv3a(const float* __restrict__ in, const float* __restrict__ in2,
            const float* __restrict__ wgtP, const float* __restrict__ aux,
            const float* __restrict__ aux2, const float* __restrict__ wb,
            float* __restrict__ out)
{
    constexpr bool FUSE = (EPI == 3);
    constexpr int NCH = IC / CH;
    constexpr int OCB = OCTOT / 4;
    constexpr int WPT = OCTOT / 4;           // float4s per tap row
    constexpr int INF = CH * 6 * 36;
    constexpr int WF  = CH * 9 * OCTOT;
    constexpr int BUFSZ = (FUSE ? 2 * INF : INF) + WF;
    __shared__ __align__(16) float sbuf[2][BUFSZ];
    __shared__ __align__(16) float wbs[FUSE ? 64 * OCTOT : 4];

    const int ocblk = blockIdx.x;
    const int n     = blockIdx.y;
    const int R0    = blockIdx.z * 4;
    const int tid   = threadIdx.x;
    const int col   = tid & 31;
    const int ocg   = tid >> 5;

    float w0 = 0.f, w1 = 0.f;
    if constexpr (FUSE) {
        w0 = __ldg(&g_w[0]); w1 = __ldg(&g_w[1]);
        for (int idx = tid; idx < 64 * OCTOT; idx += 128) {
            int o = idx % OCTOT, c = idx / OCTOT;
            wbs[c * OCTOT + o] = __ldg(wb + (ocblk * OCTOT + o) * 64 + c);
        }
    }

    const float4* in4  = (const float4*)in;
    const float4* in24 = (const float4*)in2;
    const float4* w4   = (const float4*)wgtP;

    auto stage = [&](int buf, int chunk) {
        uint32_t sb = (uint32_t)__cvta_generic_to_shared(&sbuf[buf][0]);
        #pragma unroll 1
        for (int idx = tid; idx < INF / 4; idx += 128) {
            int cc4 = idx % 9;
            int rr  = (idx / 9) % 6;
            int c   = idx / 54;
            size_t g = (((size_t)n * IC + chunk * CH + c) * 36 + R0 + 1 + rr) * 9 + cc4;
            cpa16(sb + idx * 16, in4 + g);
            if constexpr (FUSE)
                cpa16(sb + INF * 4 + idx * 16, in24 + g);
        }
        uint32_t wsb = sb + (FUSE ? 2 : 1) * INF * 4;
        #pragma unroll 1
        for (int idx = tid; idx < WF / 4; idx += 128) {
            int f   = idx % WPT;
            int tp  = (idx / WPT) % 9;
            int icl = idx / (9 * WPT);
            cpa16(wsb + idx * 16,
                  w4 + ((((chunk * CH + icl) * 9 + tp) * OC + ocblk * OCTOT) >> 2) + f);
        }
        cpcommit();
    };

    float acc[OCB][4] = {};

    stage(0, 0);
    for (int c = 0; c < NCH; c++) {
        if (c + 1 < NCH) { stage((c + 1) & 1, c + 1); cpwait1(); }
        else cpwait0();
        __syncthreads();
        float* sb = &sbuf[c & 1][0];
        if constexpr (FUSE) {
            float4* A4 = (float4*)sb;
            const float4* B4 = (const float4*)(sb + INF);
            #pragma unroll 1
            for (int idx = tid; idx < INF / 4; idx += 128) {
                float4 a = A4[idx], b = B4[idx];
                a.x = w0 * a.x + w1 * b.x;
                a.y = w0 * a.y + w1 * b.y;
                a.z = w0 * a.z + w1 * b.z;
                a.w = w0 * a.w + w1 * b.w;
                A4[idx] = a;
            }
            __syncthreads();
        }
        const float* wsm = sb + (FUSE ? 2 : 1) * INF;
        #pragma unroll
        for (int ch = 0; ch < CH; ch++) {
            float v[6][3];
            const float* sp = sb + ch * 216 + col + 1;
            #pragma unroll
            for (int rr = 0; rr < 6; rr++)
                #pragma unroll
                for (int cc = 0; cc < 3; cc++)
                    v[rr][cc] = sp[rr * 36 + cc];
            #pragma unroll
            for (int tap = 0; tap < 9; tap++) {
                int u = tap / 3, vv = tap % 3;
                const float* wp = &wsm[(ch * 9 + tap) * OCTOT + ocg * OCB];
                if constexpr (OCB == 4) {
                    float4 wv = *(const float4*)wp;
                    #pragma unroll
                    for (int k = 0; k < 4; k++) {
                        acc[0][k] += v[u + k][vv] * wv.x;
                        acc[1][k] += v[u + k][vv] * wv.y;
                        acc[2][k] += v[u + k][vv] * wv.z;
                        acc[3][k] += v[u + k][vv] * wv.w;
                    }
                } else {
                    float2 wv = *(const float2*)wp;
                    #pragma unroll
                    for (int k = 0; k < 4; k++) {
                        acc[0][k] += v[u + k][vv] * wv.x;
                        acc[1][k] += v[u + k][vv] * wv.y;
                    }
                }
            }
        }
        __syncthreads();
    }

    float bp[OCB][4] = {};
    if constexpr (FUSE) {
        const float* xb = aux2 + ((size_t)n * 64 * 32 + R0) * 32 + col;
        #pragma unroll 4
        for (int c = 0; c < 64; c++) {
            float xv[4];
            #pragma unroll
            for (int k = 0; k < 4; k++) xv[k] = __ldg(xb + k * 32);
            const float* wp = &wbs[c * OCTOT + ocg * OCB];
            #pragma unroll
            for (int o = 0; o < OCB; o++) {
                float wv = wp[o];
                #pragma unroll
                for (int k = 0; k < 4; k++) bp[o][k] += xv[k] * wv;
            }
            xb += 1024;
        }
    }

    #pragma unroll
    for (int o = 0; o < OCB; o++) {
        int og = ocblk * OCTOT + ocg * OCB + o;
        #pragma unroll
        for (int k = 0; k < 4; k++) {
            int row = R0 + k;
            float val = acc[o][k];
            if constexpr (EPI == 1) {
                val = fmaxf(val, 0.f);
                out[((size_t)(n * OC + og) * 36 + row + 2) * 36 + col + 2] = val;
            } else if constexpr (EPI == 2) {
                val = __ldg(aux + ((size_t)(n * OC + og) * 32 + row) * 32 + col) - val;
                out[((size_t)(n * OC + og) * 36 + row + 2) * 36 + col + 2] = val;
            } else {
                val = __ldg(aux + ((size_t)(n * 128 + og) * 36 + row + 2) * 36 + col + 2)
                      + val + bp[o][k];
                out[((size_t)(n * OC + og) * 32 + row) * 32 + col] = val;
            }
        }
    }
}

// ---------------------------------------------------------------------------
// cp.async double-buffered 5x5 Gram conv (M = A A^T), 64->64, OCB=2.
// Block 128 = col(32) x ocg(4); CTA = 4 rows x 8 oc.  Grid (8,4,8) = 256 CTAs.
// (round-13 geometry: measured 30.4us)
// Fused Krylov dots + FUSED recur: last CTA (atomic ticket) reduces all
// partials, runs the blocked 500-step recursion, writes g_w, resets counter.
// ---------------------------------------------------------------------------
__global__ __launch_bounds__(128)
void conv5a(const float* __restrict__ in, const float* __restrict__ T,
            float* __restrict__ out, double* __restrict__ partials,
            float* __restrict__ wout)
{
    constexpr int CH  = 8, NCH = 8;
    constexpr int INF = CH * 8 * 36;   // 2304 floats
    constexpr int WF  = CH * 25 * 8;   // 1600 floats
    __shared__ __align__(16) float sbuf[2][INF + WF];
    __shared__ int s_last;

    const int ocblk = blockIdx.x;
    const int n     = blockIdx.y;
    const int R0    = blockIdx.z * 4;
    const int tid   = threadIdx.x;
    const int col   = tid & 31;
    const int ocg   = tid >> 5;
    const int cap_base = ocg * 2;

    const float4* in4 = (const float4*)in;
    const float4* t4  = (const float4*)T;

    auto stage = [&](int buf, int chunk) {
        uint32_t sb = (uint32_t)__cvta_generic_to_shared(&sbuf[buf][0]);
        #pragma unroll 1
        for (int idx = tid; idx < INF / 4; idx += 128) {
            int cc4 = idx % 9;
            int rr  = (idx / 9) % 8;
            int c   = idx / 72;
            cpa16(sb + idx * 16,
                  in4 + (((size_t)n * 64 + chunk * CH + c) * 36 + R0 + rr) * 9 + cc4);
        }
        uint32_t wsb = sb + INF * 4;
        #pragma unroll 1
        for (int idx = tid; idx < WF / 4; idx += 128) {
            int f   = idx & 1;
            int tap = (idx >> 1) % 25;
            int al  = idx / 50;
            cpa16(wsb + idx * 16,
                  t4 + ((((chunk * CH + al) * 25 + tap) * 64 + ocblk * 8) >> 2) + f);
        }
        cpcommit();
    };

    float acc[2][4] = {};
    float rc[2][4];

    stage(0, 0);
    for (int c = 0; c < NCH; c++) {
        if (c + 1 < NCH) { stage((c + 1) & 1, c + 1); cpwait1(); }
        else cpwait0();
        __syncthreads();
        const float* sb  = &sbuf[c & 1][0];
        const float* wsm = sb + INF;
        if (c == ocblk) {
            #pragma unroll
            for (int o = 0; o < 2; o++)
                #pragma unroll
                for (int k = 0; k < 4; k++)
                    rc[o][k] = sb[(cap_base + o) * 288 + (k + 2) * 36 + col + 2];
        }
        #pragma unroll
        for (int ch = 0; ch < CH; ch++) {
            float v[8][5];
            const float* sp = sb + ch * 288 + col;
            #pragma unroll
            for (int rr = 0; rr < 8; rr++)
                #pragma unroll
                for (int dv = 0; dv < 5; dv++)
                    v[rr][dv] = sp[rr * 36 + dv];
            #pragma unroll
            for (int tap = 0; tap < 25; tap++) {
                int du = tap / 5, dv = tap % 5;
                float2 wv = *(const float2*)&wsm[(ch * 25 + tap) * 8 + ocg * 2];
                #pragma unroll
                for (int k = 0; k < 4; k++) {
                    acc[0][k] += v[k + du][dv] * wv.x;
                    acc[1][k] += v[k + du][dv] * wv.y;
                }
            }
        }
        __syncthreads();
    }

    #pragma unroll
    for (int o = 0; o < 2; o++) {
        int og = ocblk * 8 + ocg * 2 + o;
        #pragma unroll
        for (int k = 0; k < 4; k++)
            out[((size_t)(n * 64 + og) * 36 + R0 + k + 2) * 36 + col + 2] = acc[o][k];
    }

    // Fused dot products (each r-space interior element counted exactly once)
    float l0 = 0.f, l1 = 0.f, l2 = 0.f;
    #pragma unroll
    for (int o = 0; o < 2; o++)
        #pragma unroll
        for (int k = 0; k < 4; k++) {
            l0 += rc[o][k] * rc[o][k];
            l1 += rc[o][k] * acc[o][k];
            l2 += acc[o][k] * acc[o][k];
        }
    __syncthreads();
    double* red = (double*)&sbuf[0][0];
    red[tid]       = (double)l0;
    red[128 + tid] = (double)l1;
    red[256 + tid] = (double)l2;
    __syncthreads();
    for (int s = 64; s > 0; s >>= 1) {
        if (tid < s) {
            red[tid]       += red[tid + s];
            red[128 + tid] += red[128 + tid + s];
            red[256 + tid] += red[256 + tid + s];
        }
        __syncthreads();
    }
    if (tid == 0) {
        int cta = blockIdx.x + 8 * blockIdx.y + 32 * blockIdx.z;
        partials[cta * 3 + 0] = red[0];
        partials[cta * 3 + 1] = red[128];
        partials[cta * 3 + 2] = red[256];
        __threadfence();
        unsigned ticket = atomicAdd(&g_ctr, 1u);
        s_last = (ticket == NDOTCTA - 1) ? 1 : 0;
    }
    __syncthreads();

    if (s_last) {
        // Last CTA: reduce all partials, run blocked recursion, write g_w.
        __threadfence();   // acquire: see all CTAs' partial writes
        double a0 = partials[tid * 3 + 0] + partials[(tid + 128) * 3 + 0];
        double a1 = partials[tid * 3 + 1] + partials[(tid + 128) * 3 + 1];
        double a2 = partials[tid * 3 + 2] + partials[(tid + 128) * 3 + 2];
        __syncthreads();
        red[tid]       = a0;
        red[128 + tid] = a1;
        red[256 + tid] = a2;
        __syncthreads();
        for (int s = 64; s > 0; s >>= 1) {
            if (tid < s) {
                red[tid]       += red[tid + s];
                red[128 + tid] += red[128 + tid + s];
                red[256 + tid] += red[256 + tid + s];
            }
            __syncthreads();
        }
        if (tid == 0) {
            const float H00 = (float)red[0], H01 = (float)red[128],
                        H11 = (float)red[256];
            float p1 = 0.f, w0 = 0.f, w1 = 0.f;
            #pragma unroll
            for (int b = 0; b < 20; b++) {
                float nsq = H00 + p1 * (2.f * H01 + p1 * H11);
                float cc = LRF * rsqrtf(nsq);
                w0 += 25.f * cc;
                w1 += cc * (25.f * p1 - cc * 300.f);  // sum_{i<25} (p1 - i c)
                p1 -= 25.f * cc;
            }
            wout[0] = w0; wout[1] = w1;
            g_ctr = 0;                 // reset for next replay (deterministic)
        }
    }
}

extern "C" void kernel_launch(void* const* d_in, const int* in_sizes, int n_in,
                              void* d_out, int out_size)
{
    const float* x   = (const float*)d_in[0];
    const float* Wff = (const float*)d_in[1];
    const float* Wfb = (const float*)d_in[2];
    const float* Wbp = (const float*)d_in[3];
    float* out = (float*)d_out;

    float *x36, *y0, *r0, *m1, *w, *T, *WffP, *WfbP1, *WfbP2;
    double* part;
    cudaGetSymbolAddress((void**)&x36, g_x36);
    cudaGetSymbolAddress((void**)&y0, g_y0);
    cudaGetSymbolAddress((void**)&r0, g_r0);
    cudaGetSymbolAddress((void**)&m1, g_m1);
    cudaGetSymbolAddress((void**)&w,  g_w);
    cudaGetSymbolAddress((void**)&T,  g_T);
    cudaGetSymbolAddress((void**)&WffP,  g_WffP);
    cudaGetSymbolAddress((void**)&WfbP1, g_WfbP1);
    cudaGetSymbolAddress((void**)&WfbP2, g_WfbP2);
    cudaGetSymbolAddress((void**)&part, g_part);

    // setup: tgram + x36 interior fill + weight re-layout (no zeroing)
    setup_kernel<<<128, 256>>>(x, Wff, Wfb);

    // y0 = relu(conv3x3_pad1(x, W_ff)) -> padded (4,128,36,36)   [256 CTAs]
    conv3a<64, 128, 1, 16, 16><<<dim3(8, 4, 8), 128>>>(
        x36, nullptr, WffP, nullptr, nullptr, nullptr, y0);
    // r0 = x - A(pad(y0)) -> padded (4,64,36,36)                 [256 CTAs]
    conv3a<128, 64, 2, 16, 8><<<dim3(8, 4, 8), 128>>>(
        y0, nullptr, WfbP1, x, nullptr, nullptr, r0);
    // m1 = M r0 (5x5 Gram conv) + fused Krylov dots + fused recur [256 CTAs]
    conv5a<<<dim3(8, 4, 8), 128>>>(r0, T, m1, part, w);

    // out = y0 + crop(A^T (w0*r0 + w1*m1)) + conv1x1(x, W_bypass) [256 CTAs]
    // (combine fused into the conv's smem staging)
    conv3a<64, 128, 3, 8, 16><<<dim3(8, 4, 8), 128>>>(
        r0, m1, WfbP2, y0, x, Wbp, out);
}

// round 16
// speedup vs baseline: 1.6043x; 1.6043x over previous
#include <cuda_runtime.h>
#include <math.h>
#include <stdint.h>

constexpr float LRF = 0.001f;

// All feature maps stored 36x36 with logical origin (2,2).
// Borders are NEVER written by any kernel -> they remain the zero value that
// __device__ globals get at module load, on every graph replay.
constexpr int NY36 = 4 * 128 * 36 * 36;
constexpr int NRP  = 4 * 64 * 36 * 36;
constexpr int NDOTCTA = 256;

__device__ __align__(16) float g_x36[NRP];
__device__ __align__(16) float g_y0[NY36];
__device__ __align__(16) float g_r0[NRP];
__device__ __align__(16) float g_m1[NRP];
__device__ __align__(16) float g_T[64 * 25 * 64];     // [(a*25+tap)*64 + b]
__device__ __align__(16) float g_WffP[64 * 9 * 128];  // [(ic*9+tap)*128 + oc]
__device__ __align__(16) float g_WfbP1[128 * 9 * 64]; // [(ic*9+tap)*64  + oc]
__device__ __align__(16) float g_WfbP2[64 * 9 * 128]; // [(ic*9+tap)*128 + og], flipped
__device__ double g_part[NDOTCTA * 3];
__device__ float g_w[2];
__device__ unsigned g_ctr;   // ticket counter; reset to 0 by last CTA each run

// ---------------- cp.async helpers ----------------
__device__ __forceinline__ void cpa16(uint32_t d, const void* s) {
    asm volatile("cp.async.cg.shared.global [%0], [%1], 16;" :: "r"(d), "l"(s));
}
__device__ __forceinline__ void cpcommit() { asm volatile("cp.async.commit_group;"); }
__device__ __forceinline__ void cpwait1()  { asm volatile("cp.async.wait_group 1;"); }
__device__ __forceinline__ void cpwait0()  { asm volatile("cp.async.wait_group 0;"); }

// ---------------------------------------------------------------------------
// setup: blocks 0..63  -> tgram (Gram 5x5 kernel of A A^T);
//        blocks 64..127 -> x36 interior fill + weight re-layout (no zeroing)
// ---------------------------------------------------------------------------
__global__ __launch_bounds__(256)
void setup_kernel(const float* __restrict__ x, const float* __restrict__ Wff,
                  const float* __restrict__ Wfb)
{
    __shared__ float red[64 * 25];
    if (blockIdx.x < 64) {
        const int b    = blockIdx.x;
        const int a    = threadIdx.x & 63;
        const int part = threadIdx.x >> 6;

        float acc[25];
        #pragma unroll
        for (int t = 0; t < 25; t++) acc[t] = 0.f;

        for (int o = part * 32; o < part * 32 + 32; o++) {
            float wbv[9], wav[9];
            #pragma unroll
            for (int i = 0; i < 9; i++) {
                wbv[i] = __ldg(Wfb + (o * 64 + b) * 9 + i);
                wav[i] = __ldg(Wfb + (o * 64 + a) * 9 + i);
            }
            #pragma unroll
            for (int du = -2; du <= 2; du++)
                #pragma unroll
                for (int dv = -2; dv <= 2; dv++) {
                    float s = 0.f;
                    #pragma unroll
                    for (int u = 0; u < 3; u++) {
                        if (u - du < 0 || u - du > 2) continue;
                        #pragma unroll
                        for (int v = 0; v < 3; v++) {
                            if (v - dv < 0 || v - dv > 2) continue;
                            s += wbv[u * 3 + v] * wav[(u - du) * 3 + (v - dv)];
                        }
                    }
                    acc[(du + 2) * 5 + (dv + 2)] += s;
                }
        }
        if (part == 3) {
            #pragma unroll
            for (int t = 0; t < 25; t++) red[a * 25 + t] = acc[t];
        }
        __syncthreads();
        if (part == 2) {
            #pragma unroll
            for (int t = 0; t < 25; t++) red[a * 25 + t] += acc[t];
        }
        __syncthreads();
        if (part == 1) {
            #pragma unroll
            for (int t = 0; t < 25; t++) red[a * 25 + t] += acc[t];
        }
        __syncthreads();
        if (part == 0) {
            #pragma unroll
            for (int t = 0; t < 25; t++)
                g_T[((size_t)a * 25 + t) * 64 + b] = acc[t] + red[a * 25 + t];
        }
    } else {
        const int i = (blockIdx.x - 64) * 256 + threadIdx.x;
        const int stride = 64 * 256;
        // x36 interior fill (borders stay zero from static init)
        for (int j = i; j < 4 * 64 * 1024; j += stride) {
            int nc = j >> 10;
            int rc = j & 1023;
            int r = rc >> 5, c = rc & 31;
            g_x36[((size_t)nc * 36 + r + 2) * 36 + c + 2] = __ldg(x + j);
        }
        for (int j = i; j < 73728; j += stride) {
            int oc  = j % 128;
            int tap = (j / 128) % 9;
            int ic  = j / 1152;
            g_WffP[j]  = __ldg(Wff + (oc * 64 + ic) * 9 + tap);
            g_WfbP2[j] = __ldg(Wfb + (oc * 64 + ic) * 9 + (8 - tap));
        }
        for (int j = i; j < 73728; j += stride) {
            int oc  = j % 64;
            int tap = (j / 64) % 9;
            int ic  = j / 576;
            g_WfbP1[j] = __ldg(Wfb + (ic * 64 + oc) * 9 + tap);
        }
    }
}

// ---------------------------------------------------------------------------
// cp.async double-buffered 3x3 conv.  Block 128 = col(32) x ocg(4),
// OCB = OCTOT/4 oc per thread.  CTA output: 4 rows x OCTOT oc.
// Grid (OC/OCTOT, 4, 8)  -- always >= 256 CTAs.
// EPI 1: relu -> padded out.
// EPI 2: x - acc -> padded out.
// EPI 3: FUSED combine: stages BOTH in (r0) and in2 (m1) per chunk and forms
//        s = w0*r0 + w1*m1 in smem; epilogue y0 + acc + 1x1(x,wb) -> raw out.
// ---------------------------------------------------------------------------
template<int IC, int OC, int EPI, int CH, int OCTOT>
__global__ __launch_bounds__(128)
void conv3a(const float* __restrict__ in, const float* __restrict__ in2,
            const float* __restrict__ wgtP, const float* __restrict__ aux,
            const float* __restrict__ aux2, const float* __restrict__ wb,
            float* __restrict__ out)
{
    constexpr bool FUSE = (EPI == 3);
    constexpr int NCH = IC / CH;
    constexpr int OCB = OCTOT / 4;
    constexpr int WPT = OCTOT / 4;           // float4s per tap row
    constexpr int INF = CH * 6 * 36;
    constexpr int WF  = CH * 9 * OCTOT;
    constexpr int BUFSZ = (FUSE ? 2 * INF : INF) + WF;
    __shared__ __align__(16) float sbuf[2][BUFSZ];
    __shared__ __align__(16) float wbs[FUSE ? 64 * OCTOT : 4];

    const int ocblk = blockIdx.x;
    const int n     = blockIdx.y;
    const int R0    = blockIdx.z * 4;
    const int tid   = threadIdx.x;
    const int col   = tid & 31;
    const int ocg   = tid >> 5;

    float w0 = 0.f, w1 = 0.f;
    if constexpr (FUSE) {
        w0 = __ldg(&g_w[0]); w1 = __ldg(&g_w[1]);
        for (int idx = tid; idx < 64 * OCTOT; idx += 128) {
            int o = idx % OCTOT, c = idx / OCTOT;
            wbs[c * OCTOT + o] = __ldg(wb + (ocblk * OCTOT + o) * 64 + c);
        }
    }

    const float4* in4  = (const float4*)in;
    const float4* in24 = (const float4*)in2;
    const float4* w4   = (const float4*)wgtP;

    auto stage = [&](int buf, int chunk) {
        uint32_t sb = (uint32_t)__cvta_generic_to_shared(&sbuf[buf][0]);
        #pragma unroll 1
        for (int idx = tid; idx < INF / 4; idx += 128) {
            int cc4 = idx % 9;
            int rr  = (idx / 9) % 6;
            int c   = idx / 54;
            size_t g = (((size_t)n * IC + chunk * CH + c) * 36 + R0 + 1 + rr) * 9 + cc4;
            cpa16(sb + idx * 16, in4 + g);
            if constexpr (FUSE)
                cpa16(sb + INF * 4 + idx * 16, in24 + g);
        }
        uint32_t wsb = sb + (FUSE ? 2 : 1) * INF * 4;
        #pragma unroll 1
        for (int idx = tid; idx < WF / 4; idx += 128) {
            int f   = idx % WPT;
            int tp  = (idx / WPT) % 9;
            int icl = idx / (9 * WPT);
            cpa16(wsb + idx * 16,
                  w4 + ((((chunk * CH + icl) * 9 + tp) * OC + ocblk * OCTOT) >> 2) + f);
        }
        cpcommit();
    };

    float acc[OCB][4] = {};

    stage(0, 0);
    for (int c = 0; c < NCH; c++) {
        if (c + 1 < NCH) { stage((c + 1) & 1, c + 1); cpwait1(); }
        else cpwait0();
        __syncthreads();
        float* sb = &sbuf[c & 1][0];
        if constexpr (FUSE) {
            float4* A4 = (float4*)sb;
            const float4* B4 = (const float4*)(sb + INF);
            #pragma unroll 1
            for (int idx = tid; idx < INF / 4; idx += 128) {
                float4 a = A4[idx], b = B4[idx];
                a.x = w0 * a.x + w1 * b.x;
                a.y = w0 * a.y + w1 * b.y;
                a.z = w0 * a.z + w1 * b.z;
                a.w = w0 * a.w + w1 * b.w;
                A4[idx] = a;
            }
            __syncthreads();
        }
        const float* wsm = sb + (FUSE ? 2 : 1) * INF;
        #pragma unroll
        for (int ch = 0; ch < CH; ch++) {
            float v[6][3];
            const float* sp = sb + ch * 216 + col + 1;
            #pragma unroll
            for (int rr = 0; rr < 6; rr++)
                #pragma unroll
                for (int cc = 0; cc < 3; cc++)
                    v[rr][cc] = sp[rr * 36 + cc];
            #pragma unroll
            for (int tap = 0; tap < 9; tap++) {
                int u = tap / 3, vv = tap % 3;
                const float* wp = &wsm[(ch * 9 + tap) * OCTOT + ocg * OCB];
                if constexpr (OCB == 4) {
                    float4 wv = *(const float4*)wp;
                    #pragma unroll
                    for (int k = 0; k < 4; k++) {
                        acc[0][k] += v[u + k][vv] * wv.x;
                        acc[1][k] += v[u + k][vv] * wv.y;
                        acc[2][k] += v[u + k][vv] * wv.z;
                        acc[3][k] += v[u + k][vv] * wv.w;
                    }
                } else {
                    float2 wv = *(const float2*)wp;
                    #pragma unroll
                    for (int k = 0; k < 4; k++) {
                        acc[0][k] += v[u + k][vv] * wv.x;
                        acc[1][k] += v[u + k][vv] * wv.y;
                    }
                }
            }
        }
        __syncthreads();
    }

    float bp[OCB][4] = {};
    if constexpr (FUSE) {
        const float* xb = aux2 + ((size_t)n * 64 * 32 + R0) * 32 + col;
        #pragma unroll 4
        for (int c = 0; c < 64; c++) {
            float xv[4];
            #pragma unroll
            for (int k = 0; k < 4; k++) xv[k] = __ldg(xb + k * 32);
            const float* wp = &wbs[c * OCTOT + ocg * OCB];
            #pragma unroll
            for (int o = 0; o < OCB; o++) {
                float wv = wp[o];
                #pragma unroll
                for (int k = 0; k < 4; k++) bp[o][k] += xv[k] * wv;
            }
            xb += 1024;
        }
    }

    #pragma unroll
    for (int o = 0; o < OCB; o++) {
        int og = ocblk * OCTOT + ocg * OCB + o;
        #pragma unroll
        for (int k = 0; k < 4; k++) {
            int row = R0 + k;
            float val = acc[o][k];
            if constexpr (EPI == 1) {
                val = fmaxf(val, 0.f);
                out[((size_t)(n * OC + og) * 36 + row + 2) * 36 + col + 2] = val;
            } else if constexpr (EPI == 2) {
                val = __ldg(aux + ((size_t)(n * OC + og) * 32 + row) * 32 + col) - val;
                out[((size_t)(n * OC + og) * 36 + row + 2) * 36 + col + 2] = val;
            } else {
                val = __ldg(aux + ((size_t)(n * 128 + og) * 36 + row + 2) * 36 + col + 2)
                      + val + bp[o][k];
                out[((size_t)(n * OC + og) * 32 + row) * 32 + col] = val;
            }
        }
    }
}

// ---------------------------------------------------------------------------
// cp.async double-buffered 5x5 Gram conv (M = A A^T), 64->64, OCB=2.
// Block 128 = col(32) x ocg(4); CTA = 4 rows x 8 oc.  Grid (8,4,8) = 256 CTAs.
// (round-13 geometry: measured 30.4us at healthy clocks)
// Fused Krylov dots + FUSED recur: last CTA (atomic ticket) reduces all
// partials, runs the blocked 500-step recursion, writes g_w, resets counter.
// ---------------------------------------------------------------------------
__global__ __launch_bounds__(128)
void conv5a(const float* __restrict__ in, const float* __restrict__ T,
            float* __restrict__ out, double* __restrict__ partials,
            float* __restrict__ wout)
{
    constexpr int CH  = 8, NCH = 8;
    constexpr int INF = CH * 8 * 36;   // 2304 floats
    constexpr int WF  = CH * 25 * 8;   // 1600 floats
    __shared__ __align__(16) float sbuf[2][INF + WF];
    __shared__ int s_last;

    const int ocblk = blockIdx.x;
    const int n     = blockIdx.y;
    const int R0    = blockIdx.z * 4;
    const int tid   = threadIdx.x;
    const int col   = tid & 31;
    const int ocg   = tid >> 5;
    const int cap_base = ocg * 2;

    const float4* in4 = (const float4*)in;
    const float4* t4  = (const float4*)T;

    auto stage = [&](int buf, int chunk) {
        uint32_t sb = (uint32_t)__cvta_generic_to_shared(&sbuf[buf][0]);
        #pragma unroll 1
        for (int idx = tid; idx < INF / 4; idx += 128) {
            int cc4 = idx % 9;
            int rr  = (idx / 9) % 8;
            int c   = idx / 72;
            cpa16(sb + idx * 16,
                  in4 + (((size_t)n * 64 + chunk * CH + c) * 36 + R0 + rr) * 9 + cc4);
        }
        uint32_t wsb = sb + INF * 4;
        #pragma unroll 1
        for (int idx = tid; idx < WF / 4; idx += 128) {
            int f   = idx & 1;
            int tap = (idx >> 1) % 25;
            int al  = idx / 50;
            cpa16(wsb + idx * 16,
                  t4 + ((((chunk * CH + al) * 25 + tap) * 64 + ocblk * 8) >> 2) + f);
        }
        cpcommit();
    };

    float acc[2][4] = {};
    float rc[2][4];

    stage(0, 0);
    for (int c = 0; c < NCH; c++) {
        if (c + 1 < NCH) { stage((c + 1) & 1, c + 1); cpwait1(); }
        else cpwait0();
        __syncthreads();
        const float* sb  = &sbuf[c & 1][0];
        const float* wsm = sb + INF;
        if (c == ocblk) {
            #pragma unroll
            for (int o = 0; o < 2; o++)
                #pragma unroll
                for (int k = 0; k < 4; k++)
                    rc[o][k] = sb[(cap_base + o) * 288 + (k + 2) * 36 + col + 2];
        }
        #pragma unroll
        for (int ch = 0; ch < CH; ch++) {
            float v[8][5];
            const float* sp = sb + ch * 288 + col;
            #pragma unroll
            for (int rr = 0; rr < 8; rr++)
                #pragma unroll
                for (int dv = 0; dv < 5; dv++)
                    v[rr][dv] = sp[rr * 36 + dv];
            #pragma unroll
            for (int tap = 0; tap < 25; tap++) {
                int du = tap / 5, dv = tap % 5;
                float2 wv = *(const float2*)&wsm[(ch * 25 + tap) * 8 + ocg * 2];
                #pragma unroll
                for (int k = 0; k < 4; k++) {
                    acc[0][k] += v[k + du][dv] * wv.x;
                    acc[1][k] += v[k + du][dv] * wv.y;
                }
            }
        }
        __syncthreads();
    }

    #pragma unroll
    for (int o = 0; o < 2; o++) {
        int og = ocblk * 8 + ocg * 2 + o;
        #pragma unroll
        for (int k = 0; k < 4; k++)
            out[((size_t)(n * 64 + og) * 36 + R0 + k + 2) * 36 + col + 2] = acc[o][k];
    }

    // Fused dot products (each r-space interior element counted exactly once)
    float l0 = 0.f, l1 = 0.f, l2 = 0.f;
    #pragma unroll
    for (int o = 0; o < 2; o++)
        #pragma unroll
        for (int k = 0; k < 4; k++) {
            l0 += rc[o][k] * rc[o][k];
            l1 += rc[o][k] * acc[o][k];
            l2 += acc[o][k] * acc[o][k];
        }
    __syncthreads();
    double* red = (double*)&sbuf[0][0];
    red[tid]       = (double)l0;
    red[128 + tid] = (double)l1;
    red[256 + tid] = (double)l2;
    __syncthreads();
    for (int s = 64; s > 0; s >>= 1) {
        if (tid < s) {
            red[tid]       += red[tid + s];
            red[128 + tid] += red[128 + tid + s];
            red[256 + tid] += red[256 + tid + s];
        }
        __syncthreads();
    }
    if (tid == 0) {
        int cta = blockIdx.x + 8 * blockIdx.y + 32 * blockIdx.z;
        partials[cta * 3 + 0] = red[0];
        partials[cta * 3 + 1] = red[128];
        partials[cta * 3 + 2] = red[256];
        __threadfence();
        unsigned ticket = atomicAdd(&g_ctr, 1u);
        s_last = (ticket == NDOTCTA - 1) ? 1 : 0;
    }
    __syncthreads();

    if (s_last) {
        // Last CTA: reduce all partials, run blocked recursion, write g_w.
        __threadfence();   // acquire: see all CTAs' partial writes
        double a0 = partials[tid * 3 + 0] + partials[(tid + 128) * 3 + 0];
        double a1 = partials[tid * 3 + 1] + partials[(tid + 128) * 3 + 1];
        double a2 = partials[tid * 3 + 2] + partials[(tid + 128) * 3 + 2];
        __syncthreads();
        red[tid]       = a0;
        red[128 + tid] = a1;
        red[256 + tid] = a2;
        __syncthreads();
        for (int s = 64; s > 0; s >>= 1) {
            if (tid < s) {
                red[tid]       += red[tid + s];
                red[128 + tid] += red[128 + tid + s];
                red[256 + tid] += red[256 + tid + s];
            }
            __syncthreads();
        }
        if (tid == 0) {
            const float H00 = (float)red[0], H01 = (float)red[128],
                        H11 = (float)red[256];
            float p1 = 0.f, w0 = 0.f, w1 = 0.f;
            #pragma unroll
            for (int b = 0; b < 20; b++) {
                float nsq = H00 + p1 * (2.f * H01 + p1 * H11);
                float cc = LRF * rsqrtf(nsq);
                w0 += 25.f * cc;
                w1 += cc * (25.f * p1 - cc * 300.f);  // sum_{i<25} (p1 - i c)
                p1 -= 25.f * cc;
            }
            wout[0] = w0; wout[1] = w1;
            g_ctr = 0;                 // reset for next replay (deterministic)
        }
    }
}

extern "C" void kernel_launch(void* const* d_in, const int* in_sizes, int n_in,
                              void* d_out, int out_size)
{
    const float* x   = (const float*)d_in[0];
    const float* Wff = (const float*)d_in[1];
    const float* Wfb = (const float*)d_in[2];
    const float* Wbp = (const float*)d_in[3];
    float* out = (float*)d_out;

    float *x36, *y0, *r0, *m1, *w, *T, *WffP, *WfbP1, *WfbP2;
    double* part;
    cudaGetSymbolAddress((void**)&x36, g_x36);
    cudaGetSymbolAddress((void**)&y0, g_y0);
    cudaGetSymbolAddress((void**)&r0, g_r0);
    cudaGetSymbolAddress((void**)&m1, g_m1);
    cudaGetSymbolAddress((void**)&w,  g_w);
    cudaGetSymbolAddress((void**)&T,  g_T);
    cudaGetSymbolAddress((void**)&WffP,  g_WffP);
    cudaGetSymbolAddress((void**)&WfbP1, g_WfbP1);
    cudaGetSymbolAddress((void**)&WfbP2, g_WfbP2);
    cudaGetSymbolAddress((void**)&part, g_part);

    // setup: tgram + x36 interior fill + weight re-layout (no zeroing)
    setup_kernel<<<128, 256>>>(x, Wff, Wfb);

    // y0 = relu(conv3x3_pad1(x, W_ff)) -> padded (4,128,36,36)   [256 CTAs]
    conv3a<64, 128, 1, 16, 16><<<dim3(8, 4, 8), 128>>>(
        x36, nullptr, WffP, nullptr, nullptr, nullptr, y0);
    // r0 = x - A(pad(y0)) -> padded (4,64,36,36)                 [256 CTAs]
    conv3a<128, 64, 2, 16, 8><<<dim3(8, 4, 8), 128>>>(
        y0, nullptr, WfbP1, x, nullptr, nullptr, r0);
    // m1 = M r0 (5x5 Gram conv) + fused Krylov dots + fused recur [256 CTAs]
    conv5a<<<dim3(8, 4, 8), 128>>>(r0, T, m1, part, w);

    // out = y0 + crop(A^T (w0*r0 + w1*m1)) + conv1x1(x, W_bypass) [256 CTAs]
    // (combine fused into the conv's smem staging)
    conv3a<64, 128, 3, 8, 16><<<dim3(8, 4, 8), 128>>>(
        r0, m1, WfbP2, y0, x, Wbp, out);
}